// round 12
// baseline (speedup 1.0000x reference)
#include <cuda_runtime.h>
#include <cuda_bf16.h>
#include <cstdint>

// LayerwiseLowRankUplift: out = z + U_l (V_l^T z), per-sample layer l.
// B=2048, H=2048, R=64, L=32.
// R11: M=64 sample tiles (match ~64 samples/layer), coalesced V transpose,
// warp-level bf16 mma.sync, fp32 accum + fp32 z add.

#define HDIM 2048
#define RDIM 64
#define LNUM 32
#define BMAX 2048

#define KSPLIT 8
#define KRANGE (HDIM / KSPLIT)   // 256
#define KC     64                // K chunk in smem per fill

#define RS 72                    // smem row stride in bf16 (144 B)
#define RSW 36                   // row stride in uint32 words

// ---- scratch ----
__device__ int   g_counts[LNUM];
__device__ int   g_index[LNUM][BMAX];
__device__ float g_projp[KSPLIT][BMAX][RDIM];   // 4 MB partials
__device__ float g_proj[BMAX][RDIM];

__device__ __forceinline__ uint32_t pack_bf2(float lo, float hi) {
    uint32_t r;
    asm("cvt.rn.bf16x2.f32 %0, %1, %2;" : "=r"(r) : "f"(hi), "f"(lo));
    return r;
}

// D = A*B + D : m16n8k16, bf16 in, fp32 accum
#define MMA16816(c, a0, a1, a2, a3, b0, b1) \
    asm volatile("mma.sync.aligned.m16n8k16.row.col.f32.bf16.bf16.f32 " \
        "{%0,%1,%2,%3}, {%4,%5,%6,%7}, {%8,%9}, {%0,%1,%2,%3};" \
        : "+f"((c)[0]), "+f"((c)[1]), "+f"((c)[2]), "+f"((c)[3]) \
        : "r"(a0), "r"(a1), "r"(a2), "r"(a3), "r"(b0), "r"(b1))

// ============================================================
// Kernel 0: bucket sample indices by layer (warp-aggregated atomics).
// ============================================================
__global__ __launch_bounds__(256) void bucket_kernel(const int* __restrict__ ids, int B) {
    __shared__ int cur;
    const int l = blockIdx.x;
    const int lane = threadIdx.x & 31;
    if (threadIdx.x == 0) cur = 0;
    __syncthreads();
    for (int i = threadIdx.x; i < B; i += 256) {
        bool m = (ids[i] == l);
        unsigned bal = __ballot_sync(0xffffffffu, m);
        if (bal) {
            int leader = __ffs(bal) - 1;
            int base = 0;
            if (lane == leader) base = atomicAdd(&cur, __popc(bal));
            base = __shfl_sync(0xffffffffu, base, leader);
            if (m) g_index[l][base + __popc(bal & ((1u << lane) - 1u))] = i;
        }
    }
    __syncthreads();
    if (threadIdx.x == 0) g_counts[l] = cur;
}

// ============================================================
// Kernel A: proj partials. projp[ks][b][r] = sum_{k in split} z[b][k]*v[l][k][r]
// grid (LNUM, 4, KSPLIT), 256 threads (8 warps).
// Tile: M=64 samples x N=64 r x K=256 (chunks of 64).
// Warp w: M-stripe (w&3)*16 rows, N-half (w>>2)*32 cols.
// ============================================================
__global__ __launch_bounds__(256) void proj_mma(const float* __restrict__ z,
                                                const float* __restrict__ v) {
    const int l = blockIdx.x;
    const int n = g_counts[l];
    const int s0 = blockIdx.y * 64;
    if (s0 >= n) return;
    const int k0 = blockIdx.z * KRANGE;

    __shared__ __align__(16) __nv_bfloat16 Zt[64 * RS];
    __shared__ __align__(16) __nv_bfloat16 Vt[64 * RS];
    __shared__ int sidx[64];

    const int tid = threadIdx.x, wid = tid >> 5, lane = tid & 31;
    const int qr = lane >> 2, qc = lane & 3;
    const int m0 = (wid & 3) * 16;
    const int nh = wid >> 2;
    if (tid < 64) {
        int j = s0 + tid;
        sidx[tid] = g_index[l][j < n ? j : n - 1];
    }
    __syncthreads();

    float acc[4][4];
#pragma unroll
    for (int t = 0; t < 4; t++)
#pragma unroll
        for (int j = 0; j < 4; j++) acc[t][j] = 0.f;

    const float* vbase = v + (size_t)l * HDIM * RDIM;
    const uint32_t* Z32 = (const uint32_t*)Zt;
    const uint32_t* V32 = (const uint32_t*)Vt;

    for (int kc = 0; kc < KRANGE; kc += KC) {
        if (kc) __syncthreads();   // smem reuse
        // --- fill Z: row = tid>>2 (0..63), q = tid&3 covers 16 k ---
        {
            const int row = tid >> 2, q = tid & 3;
            const float4* src = (const float4*)(z + (size_t)sidx[row] * HDIM
                                                + k0 + kc + q * 16);
            uint2* dst = (uint2*)(Zt + row * RS + q * 16);
#pragma unroll
            for (int j = 0; j < 4; j++) {
                float4 x = src[j];
                dst[j] = make_uint2(pack_bf2(x.x, x.y), pack_bf2(x.z, x.w));
            }
        }
        // --- fill V^T: coalesced float4 loads of v rows, smem scatter ---
        {
#pragma unroll
            for (int i = 0; i < 4; i++) {
                int gid = tid + 256 * i;
                int k  = gid >> 4;            // chunk-local k (0..63)
                int r4 = (gid & 15) * 4;
                float4 x = *(const float4*)(vbase + (size_t)(k0 + kc + k) * RDIM + r4);
                Vt[(r4 + 0) * RS + k] = __float2bfloat16(x.x);
                Vt[(r4 + 1) * RS + k] = __float2bfloat16(x.y);
                Vt[(r4 + 2) * RS + k] = __float2bfloat16(x.z);
                Vt[(r4 + 3) * RS + k] = __float2bfloat16(x.w);
            }
        }
        __syncthreads();

#pragma unroll
        for (int kt = 0; kt < KC / 16; kt++) {
            uint32_t a0 = Z32[(m0 + qr) * RSW + kt * 8 + qc];
            uint32_t a1 = Z32[(m0 + qr + 8) * RSW + kt * 8 + qc];
            uint32_t a2 = Z32[(m0 + qr) * RSW + kt * 8 + 4 + qc];
            uint32_t a3 = Z32[(m0 + qr + 8) * RSW + kt * 8 + 4 + qc];
#pragma unroll
            for (int nt = 0; nt < 4; nt++) {
                int br = nh * 32 + nt * 8 + qr;
                uint32_t b0 = V32[br * RSW + kt * 8 + qc];
                uint32_t b1 = V32[br * RSW + kt * 8 + 4 + qc];
                MMA16816(acc[nt], a0, a1, a2, a3, b0, b1);
            }
        }
    }

    // epilogue
    const int ks = blockIdx.z;
    const int r1 = m0 + qr, r2 = r1 + 8;
    const bool v1 = (s0 + r1 < n), v2 = (s0 + r2 < n);
    float* p1 = g_projp[ks][sidx[r1]];
    float* p2 = g_projp[ks][sidx[r2]];
#pragma unroll
    for (int nt = 0; nt < 4; nt++) {
        int c = nh * 32 + nt * 8 + 2 * qc;
        if (v1) *(float2*)(p1 + c) = make_float2(acc[nt][0], acc[nt][1]);
        if (v2) *(float2*)(p2 + c) = make_float2(acc[nt][2], acc[nt][3]);
    }
}

// ============================================================
// Kernel A2: reduce K-split partials (fixed order -> deterministic)
// ============================================================
__global__ __launch_bounds__(256) void reduce_kernel() {
    const int idx = blockIdx.x * 256 + threadIdx.x;   // float4 index
    const float4* p = (const float4*)g_projp;
    const int stride = BMAX * RDIM / 4;
    float4 a = p[idx];
#pragma unroll
    for (int s = 1; s < KSPLIT; s++) {
        float4 b = p[s * stride + idx];
        a.x += b.x; a.y += b.y; a.z += b.z; a.w += b.w;
    }
    ((float4*)g_proj)[idx] = a;
}

// ============================================================
// Kernel B: out[b][h] = z[b][h] + sum_r proj[b][r] * u[l][h][r]
// grid (LNUM, 4, HDIM/128), 256 threads (8 warps).
// Tile: M=64 samples x N=128 h x K=64.
// Warp w: M-stripe (w&3)*16 rows, N-half (w>>2)*64 h (8 n-tiles).
// ============================================================
__global__ __launch_bounds__(256) void delta_mma(const float* __restrict__ z,
                                                 const float* __restrict__ u,
                                                 float* __restrict__ out) {
    const int l = blockIdx.x;
    const int n = g_counts[l];
    const int s0 = blockIdx.y * 64;
    if (s0 >= n) return;
    const int hb = blockIdx.z * 128;

    __shared__ __align__(16) __nv_bfloat16 Pt[64 * RS];
    __shared__ __align__(16) __nv_bfloat16 Ut[128 * RS];
    __shared__ int sidx[64];

    const int tid = threadIdx.x, wid = tid >> 5, lane = tid & 31;
    const int qr = lane >> 2, qc = lane & 3;
    const int m0 = (wid & 3) * 16;
    const int nh = wid >> 2;
    if (tid < 64) {
        int j = s0 + tid;
        sidx[tid] = g_index[l][j < n ? j : n - 1];
    }
    __syncthreads();

    // --- fill P (gathered proj rows): row = tid>>2, q = tid&3 covers 16 r ---
    {
        const int row = tid >> 2, q = tid & 3;
        const float4* src = (const float4*)(g_proj[sidx[row]] + q * 16);
        uint2* dst = (uint2*)(Pt + row * RS + q * 16);
#pragma unroll
        for (int j = 0; j < 4; j++) {
            float4 x = src[j];
            dst[j] = make_uint2(pack_bf2(x.x, x.y), pack_bf2(x.z, x.w));
        }
    }
    // --- fill U (natural K-major rows): row = tid>>1, half = tid&1 ---
    {
        const int row = tid >> 1, half = tid & 1;
        const float4* src = (const float4*)(u + ((size_t)l * HDIM + hb + row) * RDIM
                                            + half * 32);
        uint2* dst = (uint2*)(Ut + row * RS + half * 32);
#pragma unroll
        for (int j = 0; j < 8; j++) {
            float4 x = src[j];
            dst[j] = make_uint2(pack_bf2(x.x, x.y), pack_bf2(x.z, x.w));
        }
    }
    __syncthreads();

    const uint32_t* P32 = (const uint32_t*)Pt;
    const uint32_t* U32 = (const uint32_t*)Ut;

    // hoist A fragments for all 4 k-tiles (K=64)
    uint32_t a[4][4];
#pragma unroll
    for (int kt = 0; kt < 4; kt++) {
        a[kt][0] = P32[(m0 + qr) * RSW + kt * 8 + qc];
        a[kt][1] = P32[(m0 + qr + 8) * RSW + kt * 8 + qc];
        a[kt][2] = P32[(m0 + qr) * RSW + kt * 8 + 4 + qc];
        a[kt][3] = P32[(m0 + qr + 8) * RSW + kt * 8 + 4 + qc];
    }

    const int r1 = m0 + qr, r2 = r1 + 8;
    const bool v1 = (s0 + r1 < n), v2 = (s0 + r2 < n);
    const size_t o1 = (size_t)sidx[r1] * HDIM + hb;
    const size_t o2 = (size_t)sidx[r2] * HDIM + hb;

#pragma unroll
    for (int nt = 0; nt < 8; nt++) {
        float acc[4] = {0.f, 0.f, 0.f, 0.f};
#pragma unroll
        for (int kt = 0; kt < 4; kt++) {
            int br = nh * 64 + nt * 8 + qr;
            uint32_t b0 = U32[br * RSW + kt * 8 + qc];
            uint32_t b1 = U32[br * RSW + kt * 8 + 4 + qc];
            MMA16816(acc, a[kt][0], a[kt][1], a[kt][2], a[kt][3], b0, b1);
        }
        const int c = nh * 64 + nt * 8 + 2 * qc;
        if (v1) {
            float2 zz = *(const float2*)(z + o1 + c);
            *(float2*)(out + o1 + c) = make_float2(zz.x + acc[0], zz.y + acc[1]);
        }
        if (v2) {
            float2 zz = *(const float2*)(z + o2 + c);
            *(float2*)(out + o2 + c) = make_float2(zz.x + acc[2], zz.y + acc[3]);
        }
    }
}

// ============================================================
extern "C" void kernel_launch(void* const* d_in, const int* in_sizes, int n_in,
                              void* d_out, int out_size) {
    const float* z   = (const float*)d_in[0];
    const int*   lid = (const int*)d_in[1];
    const float* u   = (const float*)d_in[2];
    const float* v   = (const float*)d_in[3];
    float* out = (float*)d_out;
    const int B = in_sizes[1];

    bucket_kernel<<<LNUM, 256>>>(lid, B);
    proj_mma<<<dim3(LNUM, 4, KSPLIT), 256>>>(z, v);
    reduce_kernel<<<(BMAX * RDIM / 4) / 256, 256>>>();
    delta_mma<<<dim3(LNUM, 4, HDIM / 128), 256>>>(z, u, out);
}

// round 17
// speedup vs baseline: 1.2187x; 1.2187x over previous
#include <cuda_runtime.h>
#include <cuda_bf16.h>
#include <cstdint>

// LayerwiseLowRankUplift: out = z + U_l (V_l^T z), per-sample layer l.
// B=2048, H=2048, R=64, L=32.
// R12/R16: weight-resident CTAs. delta: CTA=(layer,htile), U in smem once,
// loop sample tiles. proj: CTA=(layer,ksplit), V^T in smem once, loop sample
// tiles. bf16 mma.sync, fp32 accum, fp32 z add. z prefetched ahead of MMA.

#define HDIM 2048
#define RDIM 64
#define LNUM 32
#define BMAX 2048

#define KSPLIT 16
#define KRANGE (HDIM / KSPLIT)   // 128

// 64-col tiles (k=64 or r=64): stride 72 bf16 (144 B)
#define RS  72
#define RSW 36
// 128-col tiles (k=128): stride 136 bf16 (272 B)
#define RS2  136
#define RSW2 68

// ---- scratch ----
__device__ int   g_counts[LNUM];
__device__ int   g_index[LNUM][BMAX];
__device__ float g_projp[KSPLIT][BMAX][RDIM];   // 8 MB partials
__device__ float g_proj[BMAX][RDIM];

__device__ __forceinline__ uint32_t pack_bf2(float lo, float hi) {
    uint32_t r;
    asm("cvt.rn.bf16x2.f32 %0, %1, %2;" : "=r"(r) : "f"(hi), "f"(lo));
    return r;
}

// D = A*B + D : m16n8k16, bf16 in, fp32 accum
#define MMA16816(c, a0, a1, a2, a3, b0, b1) \
    asm volatile("mma.sync.aligned.m16n8k16.row.col.f32.bf16.bf16.f32 " \
        "{%0,%1,%2,%3}, {%4,%5,%6,%7}, {%8,%9}, {%0,%1,%2,%3};" \
        : "+f"((c)[0]), "+f"((c)[1]), "+f"((c)[2]), "+f"((c)[3]) \
        : "r"(a0), "r"(a1), "r"(a2), "r"(a3), "r"(b0), "r"(b1))

// ============================================================
// Kernel 0: bucket sample indices by layer (warp-aggregated atomics).
// ============================================================
__global__ __launch_bounds__(256) void bucket_kernel(const int* __restrict__ ids, int B) {
    __shared__ int cur;
    const int l = blockIdx.x;
    const int lane = threadIdx.x & 31;
    if (threadIdx.x == 0) cur = 0;
    __syncthreads();
    for (int i = threadIdx.x; i < B; i += 256) {
        bool m = (ids[i] == l);
        unsigned bal = __ballot_sync(0xffffffffu, m);
        if (bal) {
            int leader = __ffs(bal) - 1;
            int base = 0;
            if (lane == leader) base = atomicAdd(&cur, __popc(bal));
            base = __shfl_sync(0xffffffffu, base, leader);
            if (m) g_index[l][base + __popc(bal & ((1u << lane) - 1u))] = i;
        }
    }
    __syncthreads();
    if (threadIdx.x == 0) g_counts[l] = cur;
}

// ============================================================
// Kernel A: proj partials. projp[ks][b][r] = sum_{k in split} z[b][k]*v[l][k][r]
// grid (LNUM, KSPLIT), 256 threads (8 warps).
// V^T resident: [64 r][128 k] bf16. Loop sample tiles of 64.
// Warp w: M-stripe (w&3)*16, N-half (w>>2)*32.
// ============================================================
__global__ __launch_bounds__(256) void proj_mma(const float* __restrict__ z,
                                                const float* __restrict__ v) {
    const int l = blockIdx.x;
    const int n = g_counts[l];
    const int k0 = blockIdx.y * KRANGE;

    __shared__ __align__(16) __nv_bfloat16 Vt[64 * RS2];   // [r][k]
    __shared__ __align__(16) __nv_bfloat16 Zt[64 * RS2];   // [s][k]
    __shared__ int sidx[64];

    const int tid = threadIdx.x, wid = tid >> 5, lane = tid & 31;
    const int qr = lane >> 2, qc = lane & 3;
    const int m0 = (wid & 3) * 16;
    const int nh = wid >> 2;

    // --- fill V^T once: coalesced float4 loads of v rows, smem scatter ---
    {
        const float* vbase = v + ((size_t)l * HDIM + k0) * RDIM;
#pragma unroll
        for (int i = 0; i < 8; i++) {
            int gid = tid + 256 * i;
            int k  = gid >> 4;            // 0..127
            int r4 = (gid & 15) * 4;
            float4 x = *(const float4*)(vbase + (size_t)k * RDIM + r4);
            Vt[(r4 + 0) * RS2 + k] = __float2bfloat16(x.x);
            Vt[(r4 + 1) * RS2 + k] = __float2bfloat16(x.y);
            Vt[(r4 + 2) * RS2 + k] = __float2bfloat16(x.z);
            Vt[(r4 + 3) * RS2 + k] = __float2bfloat16(x.w);
        }
    }

    const uint32_t* Z32 = (const uint32_t*)Zt;
    const uint32_t* V32 = (const uint32_t*)Vt;
    const int ks = blockIdx.y;

    for (int s0 = 0; s0 < n; s0 += 64) {
        if (tid < 64) {
            int j = s0 + tid;
            sidx[tid] = g_index[l][j < n ? j : n - 1];
        }
        __syncthreads();   // sidx ready; prior-iter Zt reads done
        // --- fill Z tile: row = tid>>2, q = tid&3 covers 32 k ---
        {
            const int row = tid >> 2, q = tid & 3;
            const float4* src = (const float4*)(z + (size_t)sidx[row] * HDIM
                                                + k0 + q * 32);
            uint2* dst = (uint2*)(Zt + row * RS2 + q * 32);
#pragma unroll
            for (int j = 0; j < 8; j++) {
                float4 x = src[j];
                dst[j] = make_uint2(pack_bf2(x.x, x.y), pack_bf2(x.z, x.w));
            }
        }
        __syncthreads();

        float acc[4][4];
#pragma unroll
        for (int t = 0; t < 4; t++)
#pragma unroll
            for (int j = 0; j < 4; j++) acc[t][j] = 0.f;

#pragma unroll
        for (int kt = 0; kt < KRANGE / 16; kt++) {
            uint32_t a0 = Z32[(m0 + qr) * RSW2 + kt * 8 + qc];
            uint32_t a1 = Z32[(m0 + qr + 8) * RSW2 + kt * 8 + qc];
            uint32_t a2 = Z32[(m0 + qr) * RSW2 + kt * 8 + 4 + qc];
            uint32_t a3 = Z32[(m0 + qr + 8) * RSW2 + kt * 8 + 4 + qc];
#pragma unroll
            for (int nt = 0; nt < 4; nt++) {
                int br = nh * 32 + nt * 8 + qr;
                uint32_t b0 = V32[br * RSW2 + kt * 8 + qc];
                uint32_t b1 = V32[br * RSW2 + kt * 8 + 4 + qc];
                MMA16816(acc[nt], a0, a1, a2, a3, b0, b1);
            }
        }

        // epilogue to partials
        const int r1 = m0 + qr, r2 = r1 + 8;
        const bool v1 = (s0 + r1 < n), v2 = (s0 + r2 < n);
        float* p1 = g_projp[ks][sidx[r1]];
        float* p2 = g_projp[ks][sidx[r2]];
#pragma unroll
        for (int nt = 0; nt < 4; nt++) {
            int c = nh * 32 + nt * 8 + 2 * qc;
            if (v1) *(float2*)(p1 + c) = make_float2(acc[nt][0], acc[nt][1]);
            if (v2) *(float2*)(p2 + c) = make_float2(acc[nt][2], acc[nt][3]);
        }
    }
}

// ============================================================
// Kernel A2: reduce K-split partials (fixed order -> deterministic)
// ============================================================
__global__ __launch_bounds__(256) void reduce_kernel() {
    const int idx = blockIdx.x * 256 + threadIdx.x;   // float4 index
    const float4* p = (const float4*)g_projp;
    const int stride = BMAX * RDIM / 4;
    float4 a = p[idx];
#pragma unroll
    for (int s = 1; s < KSPLIT; s++) {
        float4 b = p[s * stride + idx];
        a.x += b.x; a.y += b.y; a.z += b.z; a.w += b.w;
    }
    ((float4*)g_proj)[idx] = a;
}

// ============================================================
// Kernel B: out[b][h] = z[b][h] + sum_r proj[b][r] * u[l][h][r]
// grid (LNUM, HDIM/128), 256 threads (8 warps).
// U resident: [128 h][64 r] bf16. Loop sample tiles of 64.
// Warp w: M-stripe (w&3)*16, N-half (w>>2)*64 (8 n-tiles).
// ============================================================
__global__ __launch_bounds__(256) void delta_mma(const float* __restrict__ z,
                                                 const float* __restrict__ u,
                                                 float* __restrict__ out) {
    const int l = blockIdx.x;
    const int n = g_counts[l];
    const int hb = blockIdx.y * 128;

    __shared__ __align__(16) __nv_bfloat16 Ut[128 * RS];   // [h][r]
    __shared__ __align__(16) __nv_bfloat16 Pt[64 * RS];    // [s][r]
    __shared__ int sidx[64];

    const int tid = threadIdx.x, wid = tid >> 5, lane = tid & 31;
    const int qr = lane >> 2, qc = lane & 3;
    const int m0 = (wid & 3) * 16;
    const int nh = wid >> 2;

    // --- fill U once (natural K-major rows): row = tid>>1, half = tid&1 ---
    {
        const int row = tid >> 1, half = tid & 1;
        const float4* src = (const float4*)(u + ((size_t)l * HDIM + hb + row) * RDIM
                                            + half * 32);
        uint2* dst = (uint2*)(Ut + row * RS + half * 32);
#pragma unroll
        for (int j = 0; j < 8; j++) {
            float4 x = src[j];
            dst[j] = make_uint2(pack_bf2(x.x, x.y), pack_bf2(x.z, x.w));
        }
    }

    const uint32_t* P32 = (const uint32_t*)Pt;
    const uint32_t* U32 = (const uint32_t*)Ut;

    for (int s0 = 0; s0 < n; s0 += 64) {
        if (tid < 64) {
            int j = s0 + tid;
            sidx[tid] = g_index[l][j < n ? j : n - 1];
        }
        __syncthreads();   // sidx ready; prior-iter Pt frag reads done
        // --- fill P tile: row = tid>>2, q = tid&3 covers 16 r ---
        {
            const int row = tid >> 2, q = tid & 3;
            const float4* src = (const float4*)(g_proj[sidx[row]] + q * 16);
            uint2* dst = (uint2*)(Pt + row * RS + q * 16);
#pragma unroll
            for (int j = 0; j < 4; j++) {
                float4 x = src[j];
                dst[j] = make_uint2(pack_bf2(x.x, x.y), pack_bf2(x.z, x.w));
            }
        }
        __syncthreads();

        const int r1 = m0 + qr, r2 = r1 + 8;
        const bool v1 = (s0 + r1 < n), v2 = (s0 + r2 < n);
        const size_t o1 = (size_t)sidx[r1] * HDIM + hb;
        const size_t o2 = (size_t)sidx[r2] * HDIM + hb;

        // prefetch z for the whole stripe (independent loads -> MLP)
        float2 zv1[8], zv2[8];
#pragma unroll
        for (int nt = 0; nt < 8; nt++) {
            const int c = nh * 64 + nt * 8 + 2 * qc;
            zv1[nt] = v1 ? *(const float2*)(z + o1 + c) : make_float2(0.f, 0.f);
            zv2[nt] = v2 ? *(const float2*)(z + o2 + c) : make_float2(0.f, 0.f);
        }

        // hoist A fragments for all 4 k-tiles (K=64)
        uint32_t a[4][4];
#pragma unroll
        for (int kt = 0; kt < 4; kt++) {
            a[kt][0] = P32[(m0 + qr) * RSW + kt * 8 + qc];
            a[kt][1] = P32[(m0 + qr + 8) * RSW + kt * 8 + qc];
            a[kt][2] = P32[(m0 + qr) * RSW + kt * 8 + 4 + qc];
            a[kt][3] = P32[(m0 + qr + 8) * RSW + kt * 8 + 4 + qc];
        }

#pragma unroll
        for (int nt = 0; nt < 8; nt++) {
            float acc[4] = {0.f, 0.f, 0.f, 0.f};
#pragma unroll
            for (int kt = 0; kt < 4; kt++) {
                int br = nh * 64 + nt * 8 + qr;
                uint32_t b0 = U32[br * RSW + kt * 8 + qc];
                uint32_t b1 = U32[br * RSW + kt * 8 + 4 + qc];
                MMA16816(acc, a[kt][0], a[kt][1], a[kt][2], a[kt][3], b0, b1);
            }
            const int c = nh * 64 + nt * 8 + 2 * qc;
            if (v1) *(float2*)(out + o1 + c) =
                make_float2(zv1[nt].x + acc[0], zv1[nt].y + acc[1]);
            if (v2) *(float2*)(out + o2 + c) =
                make_float2(zv2[nt].x + acc[2], zv2[nt].y + acc[3]);
        }
    }
}

// ============================================================
extern "C" void kernel_launch(void* const* d_in, const int* in_sizes, int n_in,
                              void* d_out, int out_size) {
    const float* z   = (const float*)d_in[0];
    const int*   lid = (const int*)d_in[1];
    const float* u   = (const float*)d_in[2];
    const float* v   = (const float*)d_in[3];
    float* out = (float*)d_out;
    const int B = in_sizes[1];

    bucket_kernel<<<LNUM, 256>>>(lid, B);
    proj_mma<<<dim3(LNUM, KSPLIT), 256>>>(z, v);
    reduce_kernel<<<(BMAX * RDIM / 4) / 256, 256>>>();
    delta_mma<<<dim3(LNUM, HDIM / 128), 256>>>(z, u, out);
}